// round 11
// baseline (speedup 1.0000x reference)
#include <cuda_runtime.h>
#include <cstdint>

#define B_   16
#define CIN  32
#define COUT 64
#define H_   16
#define W_   512
#define LRELU_SLOPE 0.3f
#define BN_EPS 1e-5f

typedef unsigned long long u64;
typedef unsigned int u32;

__device__ __forceinline__ void fma2(u64 &d, u64 a, u64 b) {
    asm("fma.rn.f32x2 %0,%1,%2,%0;" : "+l"(d) : "l"(a), "l"(b));
}
__device__ __forceinline__ void upk(u64 v, float &lo, float &hi) {
    asm("mov.b64 {%0,%1},%2;" : "=f"(lo), "=f"(hi) : "l"(v));
}
__device__ __forceinline__ u64 pk2(float lo, float hi) {
    u64 r; asm("mov.b64 %0,{%1,%2};" : "=l"(r) : "f"(lo), "f"(hi)); return r;
}
// pack (lo,hi) floats -> bf16x2 (lo in low 16 bits)
__device__ __forceinline__ u32 bfpair(float lo, float hi) {
    u32 r; asm("cvt.rn.satfinite.bf16x2.f32 %0, %1, %2;" : "=r"(r) : "f"(hi), "f"(lo)); return r;
}
__device__ __forceinline__ u32 tf32_of(float f) {
    u32 r; asm("cvt.rna.tf32.f32 %0, %1;" : "=r"(r) : "f"(f)); return r;
}
__device__ __forceinline__ u32 smem_u32_of(const void* p) {
    u32 a; asm("{ .reg .u64 t; cvta.to.shared.u64 t, %1; cvt.u32.u64 %0, t; }" : "=r"(a) : "l"(p));
    return a;
}

// ---- SMEM layout (float offsets) ----
#define SQ_OFF   0                    // Q  16x512 fp32
#define SK_OFF   8192                 // K  16x520 tf32 bits (stride 520)
#define SV_OFF   16512                // V  16x512 fp32
#define SPE_OFF  24704                // PE 16x512 fp32
#define SCR_OFF  33024                // union: conv staging 32x520 (16640) | A bf16 2x(32x1024B swz); byte 132096 (1024-al)
#define SQT_OFF  49664                // Qt 32x20 tf32
#define SVN_OFF  50304                // Vn bf16 2x(16x80B) = 640 fl; byte 201216 (16-al)
#define SSUM     50944                // 2 x [32 rows][20] fp32 warp-partials
#define SWOFF    52224                // weights [4t][32ci][12] dup'd
#define SBIAS    53760
#define SMEM_FLOATS 53764
#define SMEM_BYTES  (SMEM_FLOATS * 4) // 215056 B

#define SA_BYTE  132096               // = SCR_OFF*4
#define SVN_BYTE 201216               // = SVN_OFF*4

#define XROW 520

__global__ __launch_bounds__(512, 1)
void conv_attn_fused_kernel(
    const float* __restrict__ x,
    const float* __restrict__ wq, const float* __restrict__ gq, const float* __restrict__ bq, const float* __restrict__ mq, const float* __restrict__ vq,
    const float* __restrict__ wk, const float* __restrict__ gk, const float* __restrict__ bk, const float* __restrict__ mk, const float* __restrict__ vk,
    const float* __restrict__ wv, const float* __restrict__ gv, const float* __restrict__ bv, const float* __restrict__ mv, const float* __restrict__ vv,
    const float* __restrict__ wp, const float* __restrict__ gp, const float* __restrict__ bp, const float* __restrict__ mp, const float* __restrict__ vp,
    float* __restrict__ out)
{
    extern __shared__ float sm[];
    char* smb = (char*)sm;
    const int bid = blockIdx.x;
    const int b   = bid >> 6;
    const int c   = bid & 63;
    const int tid = threadIdx.x;
    const int warp = tid >> 5, lane = tid & 31;
    const u32 smem0 = smem_u32_of(sm);

    // ---------------- BN-folded weights, duplicated taps ----------------
    if (tid < 160) {
        const int ci = tid / 5, kk = tid - ci * 5;
        const int src = c * 160 + ci * 5 + kk;
        const int dst = ci * 12 + 2 * kk;
        float s, a;
        s = gq[c] * rsqrtf(vq[c] + BN_EPS); a = wq[src] * s;
        sm[SWOFF + 0*384 + dst] = a; sm[SWOFF + 0*384 + dst + 1] = a;
        s = gk[c] * rsqrtf(vk[c] + BN_EPS); a = wk[src] * s;
        sm[SWOFF + 1*384 + dst] = a; sm[SWOFF + 1*384 + dst + 1] = a;
        s = gv[c] * rsqrtf(vv[c] + BN_EPS); a = wv[src] * s;
        sm[SWOFF + 2*384 + dst] = a; sm[SWOFF + 2*384 + dst + 1] = a;
        s = gp[c] * rsqrtf(vp[c] + BN_EPS); a = wp[src] * s;
        sm[SWOFF + 3*384 + dst] = a; sm[SWOFF + 3*384 + dst + 1] = a;
    }
    if (tid == 0) {
        float s;
        s = gq[c] * rsqrtf(vq[c] + BN_EPS); sm[SBIAS + 0] = bq[c] - mq[c] * s;
        s = gk[c] * rsqrtf(vk[c] + BN_EPS); sm[SBIAS + 1] = bk[c] - mk[c] * s;
        s = gv[c] * rsqrtf(vv[c] + BN_EPS); sm[SBIAS + 2] = bv[c] - mv[c] * s;
        s = gp[c] * rsqrtf(vp[c] + BN_EPS); sm[SBIAS + 3] = bp[c] - mp[c] * s;
    }
    if (tid < 128) {   // zero staging halos {2,3,516,517} per row
        int row = tid >> 2, q4 = tid & 3;
        int off = (q4 < 2) ? (2 + q4) : (514 + q4);
        sm[SCR_OFF + row * XROW + off] = 0.0f;
    }

    // ---------------- Conv(1x5)+BN+LeakyReLU : 8h x 8w tiles, 2 passes ----------------
    const int hgrp = tid >> 6;
    const int w0c  = (tid & 63) << 3;
    const float* xb = x + (size_t)b * CIN * H_ * W_;

    for (int hb = 0; hb < 2; hb++) {
        u64 acc2[4][4];
        #pragma unroll
        for (int t = 0; t < 4; t++)
            #pragma unroll
            for (int j = 0; j < 4; j++) acc2[t][j] = 0ull;

        for (int cib = 0; cib < 8; cib++) {
            float4 stg[8];
            #pragma unroll
            for (int it = 0; it < 8; it++) {
                int i  = tid + (it << 9);
                int ci = i >> 10, hh = (i >> 7) & 7, w4 = (i & 127) << 2;
                stg[it] = *(const float4*)&xb[(((size_t)(cib*4 + ci)) * H_ + (hb*8 + hh)) * W_ + w4];
            }
            __syncthreads();
            #pragma unroll
            for (int it = 0; it < 8; it++) {
                int i  = tid + (it << 9);
                int ci = i >> 10, hh = (i >> 7) & 7, w4 = (i & 127) << 2;
                *(float4*)&sm[SCR_OFF + (ci*8 + hh) * XROW + 4 + w4] = stg[it];
            }
            __syncthreads();

            #pragma unroll
            for (int ci4 = 0; ci4 < 4; ci4++) {
                const float* xr = &sm[SCR_OFF + (ci4*8 + hgrp) * XROW + w0c];
                float4 f0 = *(const float4*)(xr);
                float4 f1 = *(const float4*)(xr + 4);
                float4 f2 = *(const float4*)(xr + 8);
                float4 f3 = *(const float4*)(xr + 12);
                float xm[16] = {f0.x,f0.y,f0.z,f0.w, f1.x,f1.y,f1.z,f1.w,
                                f2.x,f2.y,f2.z,f2.w, f3.x,f3.y,f3.z,f3.w};
                u64 P[11];
                #pragma unroll
                for (int n = 0; n < 11; n++) P[n] = pk2(xm[n+2], xm[n+3]);
                const int cig = cib*4 + ci4;
                #pragma unroll
                for (int t = 0; t < 4; t++) {
                    const float* wr = &sm[SWOFF + t*384 + cig*12];
                    ulonglong2 wa = *(const ulonglong2*)wr;
                    ulonglong2 wb2 = *(const ulonglong2*)(wr + 4);
                    u64 wc = *(const u64*)(wr + 8);
                    u64 w5[5] = { wa.x, wa.y, wb2.x, wb2.y, wc };
                    #pragma unroll
                    for (int kk2 = 0; kk2 < 5; kk2++)
                        #pragma unroll
                        for (int jp = 0; jp < 4; jp++)
                            fma2(acc2[t][jp], P[2*jp + kk2], w5[kk2]);
                }
            }
        }
        const int h = hb*8 + hgrp;
        #pragma unroll
        for (int t = 0; t < 4; t++) {
            float bias = sm[SBIAS + t];
            float y[8];
            #pragma unroll
            for (int jp = 0; jp < 4; jp++) {
                float lo, hi; upk(acc2[t][jp], lo, hi);
                y[2*jp]   = lo + bias;
                y[2*jp+1] = hi + bias;
            }
            #pragma unroll
            for (int j = 0; j < 8; j++) y[j] = (y[j] >= 0.f) ? y[j] : LRELU_SLOPE * y[j];
            if (t == 1) {
                // K: tf32 bits, stride 520 (conflict-free B-fragment loads later)
                u32* kd = (u32*)(sm + SK_OFF) + h * 520 + w0c;
                u32 kz[8];
                #pragma unroll
                for (int j = 0; j < 8; j++) kz[j] = tf32_of(y[j]);
                *(uint4*)(kd)     = make_uint4(kz[0], kz[1], kz[2], kz[3]);
                *(uint4*)(kd + 4) = make_uint4(kz[4], kz[5], kz[6], kz[7]);
            } else {
                float* d = (t == 0) ? (sm + SQ_OFF + h * W_ + w0c)
                         : (t == 2) ? (sm + SV_OFF + h * W_ + w0c)
                                    : (sm + SPE_OFF + h * W_ + w0c);
                *(float4*)(d)     = make_float4(y[0], y[1], y[2], y[3]);
                *(float4*)(d + 4) = make_float4(y[4], y[5], y[6], y[7]);
            }
        }
    }
    __syncthreads();   // Q/K/V/PE ready; staging area becomes A-buffer

    // ---------------- Attention: tf32 HMMA S=Q^T K -> exp -> A bf16 -> bf16 HMMA V x A ----
    const int g  = lane >> 2, tg = lane & 3;
    // ldmatrix lane mapping for consume A'[v][w] (x4.trans)
    const int agrp = lane >> 3, alr = lane & 7;
    const int a_voff = (agrp & 1) << 3;
    const int a_roff = (agrp >> 1) << 3;

    float acc[2][2][4];                   // consume D[v][h] fragments
    #pragma unroll
    for (int mi = 0; mi < 2; mi++)
        #pragma unroll
        for (int ni = 0; ni < 2; ni++)
            #pragma unroll
            for (int q = 0; q < 4; q++) acc[mi][ni][q] = 0.0f;

    const u32* qtp = (const u32*)(sm + SQT_OFF);
    const u32* kp  = (const u32*)(sm + SK_OFF);

    #pragma unroll 1
    for (int i = 0; i <= 16; i++) {
        const int half = i & 1;
        if (i < 16) {
            // stage Qt[w][h] (tf32) for this block
            int wq_ = tid & 31, hq_ = tid >> 5;
            ((u32*)sm)[SQT_OFF + wq_ * 20 + hq_] =
                tf32_of(sm[SQ_OFF + hq_ * W_ + (i << 5) + wq_]);
        }
        __syncthreads();   // barrier0: Qt(i) ready; A(i-1) reads (consume) done

        if (i < 16) {
            // ---- S-MMA: S[32w x 512v] = Qt[32w x 16h] x K[16h x 512v], per warp N=32
            u32 afr[2][2][4];
            #pragma unroll
            for (int mt = 0; mt < 2; mt++) {
                int r0 = mt * 16 + g;
                #pragma unroll
                for (int kt = 0; kt < 2; kt++) {
                    int c0 = kt * 8 + tg;
                    afr[mt][kt][0] = qtp[r0 * 20 + c0];
                    afr[mt][kt][1] = qtp[(r0 + 8) * 20 + c0];
                    afr[mt][kt][2] = qtp[r0 * 20 + c0 + 4];
                    afr[mt][kt][3] = qtp[(r0 + 8) * 20 + c0 + 4];
                }
            }
            u32 bfr2[4][2][2];
            #pragma unroll
            for (int nt = 0; nt < 4; nt++) {
                int n0 = (warp << 5) + nt * 8 + g;
                #pragma unroll
                for (int kt = 0; kt < 2; kt++) {
                    int k0 = kt * 8 + tg;
                    bfr2[nt][kt][0] = kp[k0 * 520 + n0];
                    bfr2[nt][kt][1] = kp[(k0 + 4) * 520 + n0];
                }
            }
            char* aB = smb + SA_BYTE + half * 32768;
            float ps[2][2] = {{0.f, 0.f}, {0.f, 0.f}};
            #pragma unroll
            for (int mt = 0; mt < 2; mt++)
                #pragma unroll
                for (int nt = 0; nt < 4; nt++) {
                    float cf[4] = {0.f, 0.f, 0.f, 0.f};
                    #pragma unroll
                    for (int kt = 0; kt < 2; kt++)
                        asm volatile(
                            "mma.sync.aligned.m16n8k8.row.col.f32.tf32.tf32.f32 "
                            "{%0,%1,%2,%3},{%4,%5,%6,%7},{%8,%9},{%0,%1,%2,%3};"
                            : "+f"(cf[0]), "+f"(cf[1]), "+f"(cf[2]), "+f"(cf[3])
                            : "r"(afr[mt][kt][0]), "r"(afr[mt][kt][1]),
                              "r"(afr[mt][kt][2]), "r"(afr[mt][kt][3]),
                              "r"(bfr2[nt][kt][0]), "r"(bfr2[nt][kt][1]));
                    float e0 = __expf(cf[0]), e1 = __expf(cf[1]);
                    float e2 = __expf(cf[2]), e3 = __expf(cf[3]);
                    ps[mt][0] += e0 + e1;
                    ps[mt][1] += e2 + e3;
                    const int rlo = mt * 16 + g, rhi = rlo + 8;
                    const int v0 = (warp << 5) + nt * 8 + 2 * tg;
                    *(u32*)(aB + rlo * 1024 + (((u32)(v0 * 2)) ^ ((u32)((rlo & 7) << 4))))
                        = bfpair(e0, e1);
                    *(u32*)(aB + rhi * 1024 + (((u32)(v0 * 2)) ^ ((u32)((rhi & 7) << 4))))
                        = bfpair(e2, e3);
                }
            // reduce row-partials across the 4 lanes of each row group
            #pragma unroll
            for (int mt = 0; mt < 2; mt++)
                #pragma unroll
                for (int q = 0; q < 2; q++) {
                    ps[mt][q] += __shfl_xor_sync(0xffffffffu, ps[mt][q], 1);
                    ps[mt][q] += __shfl_xor_sync(0xffffffffu, ps[mt][q], 2);
                }
            if (tg == 0) {
                #pragma unroll
                for (int mt = 0; mt < 2; mt++) {
                    sm[SSUM + half * 640 + (mt * 16 + g) * 20 + warp]     = ps[mt][0];
                    sm[SSUM + half * 640 + (mt * 16 + g + 8) * 20 + warp] = ps[mt][1];
                }
            }
        }
        __syncthreads();   // barrier1: A(i) + psums(i) visible

        if (i < 16) {
            // ---- Vn[h][w] = V[h][wb+w] * rinv(w), bf16, 80B row stride
            const int wb = i << 5;
            const int h2 = tid >> 5, r = lane;
            const float* pp = &sm[SSUM + half * 640 + r * 20];
            float4 s0 = *(const float4*)(pp);
            float4 s1 = *(const float4*)(pp + 4);
            float4 s2 = *(const float4*)(pp + 8);
            float4 s3 = *(const float4*)(pp + 12);
            float ssum = ((s0.x + s0.y) + (s0.z + s0.w)) + ((s1.x + s1.y) + (s1.z + s1.w))
                       + ((s2.x + s2.y) + (s2.z + s2.w)) + ((s3.x + s3.y) + (s3.z + s3.w));
            float rinv = __fdividef(1.0f, ssum);
            float vn = sm[SV_OFF + h2 * W_ + wb + r] * rinv;
            *(unsigned short*)(smb + SVN_BYTE + half * 1280 + h2 * 80 + r * 2)
                = (unsigned short)(bfpair(vn, 0.0f) & 0xFFFFu);
        }

        if (i > 0) {
            // ---- consume block i-1 : D[v][h] += A'[v][w] * Vn[w][h]  (8 bf16 HMMA / warp)
            const int cbk = (i - 1) & 1;
            const u32 ab = smem0 + SA_BYTE + cbk * 32768;
            const u32 bb = smem0 + SVN_BYTE + cbk * 1280;
            u32 bfr[2][2][2];
            #pragma unroll
            for (int ni = 0; ni < 2; ni++)
                #pragma unroll
                for (int ks = 0; ks < 2; ks++) {
                    u32 addr = bb + (u32)((ni * 8 + (lane & 7)) * 80 + ks * 32 + ((lane >> 3) & 1) * 16);
                    asm volatile("ldmatrix.sync.aligned.m8n8.x2.shared.b16 {%0,%1}, [%2];"
                        : "=r"(bfr[ni][ks][0]), "=r"(bfr[ni][ks][1]) : "r"(addr));
                }
            #pragma unroll
            for (int mi = 0; mi < 2; mi++) {
                u32 af[2][4];
                #pragma unroll
                for (int ks = 0; ks < 2; ks++) {
                    const int r  = ks * 16 + a_roff + alr;
                    const int vb = (warp << 5) + (mi << 4) + a_voff;
                    u32 addr = ab + (u32)(r * 1024 + (((u32)(vb * 2)) ^ ((u32)(alr << 4))));
                    asm volatile("ldmatrix.sync.aligned.m8n8.x4.trans.shared.b16 {%0,%1,%2,%3}, [%4];"
                        : "=r"(af[ks][0]), "=r"(af[ks][1]), "=r"(af[ks][2]), "=r"(af[ks][3])
                        : "r"(addr));
                }
                #pragma unroll
                for (int ni = 0; ni < 2; ni++)
                    #pragma unroll
                    for (int ks = 0; ks < 2; ks++)
                        asm volatile(
                            "mma.sync.aligned.m16n8k16.row.col.f32.bf16.bf16.f32 "
                            "{%0,%1,%2,%3},{%4,%5,%6,%7},{%8,%9},{%0,%1,%2,%3};"
                            : "+f"(acc[mi][ni][0]), "+f"(acc[mi][ni][1]),
                              "+f"(acc[mi][ni][2]), "+f"(acc[mi][ni][3])
                            : "r"(af[ks][0]), "r"(af[ks][1]), "r"(af[ks][2]), "r"(af[ks][3]),
                              "r"(bfr[ni][ks][0]), "r"(bfr[ni][ks][1]));
            }
        }
    }

    // ---------------- Epilogue: D + PE -> gmem straight from fragments ----------------
    float* og = out + (size_t)bid * (H_ * W_);
    {
        const int vb = (warp << 5) + (lane >> 2);
        const int hb2 = (lane & 3) << 1;
        #pragma unroll
        for (int mi = 0; mi < 2; mi++)
            #pragma unroll
            for (int ni = 0; ni < 2; ni++) {
                const int v = vb + (mi << 4);
                const int h = hb2 + (ni << 3);
                og[h * W_ + v]           = acc[mi][ni][0] + sm[SPE_OFF + h * W_ + v];
                og[(h + 1) * W_ + v]     = acc[mi][ni][1] + sm[SPE_OFF + (h + 1) * W_ + v];
                og[h * W_ + v + 8]       = acc[mi][ni][2] + sm[SPE_OFF + h * W_ + v + 8];
                og[(h + 1) * W_ + v + 8] = acc[mi][ni][3] + sm[SPE_OFF + (h + 1) * W_ + v + 8];
            }
    }
}

extern "C" void kernel_launch(void* const* d_in, const int* in_sizes, int n_in,
                              void* d_out, int out_size)
{
    cudaFuncSetAttribute(conv_attn_fused_kernel,
                         cudaFuncAttributeMaxDynamicSharedMemorySize, SMEM_BYTES);

    const float* x  = (const float*)d_in[0];
    const float* wq = (const float*)d_in[1];
    const float* gq = (const float*)d_in[2];
    const float* bq = (const float*)d_in[3];
    const float* mq = (const float*)d_in[4];
    const float* vq = (const float*)d_in[5];
    const float* wk = (const float*)d_in[6];
    const float* gk = (const float*)d_in[7];
    const float* bk = (const float*)d_in[8];
    const float* mk = (const float*)d_in[9];
    const float* vk = (const float*)d_in[10];
    const float* wv = (const float*)d_in[11];
    const float* gv = (const float*)d_in[12];
    const float* bv = (const float*)d_in[13];
    const float* mv = (const float*)d_in[14];
    const float* vv = (const float*)d_in[15];
    const float* wp = (const float*)d_in[16];
    const float* gp = (const float*)d_in[17];
    const float* bp = (const float*)d_in[18];
    const float* mp = (const float*)d_in[19];
    const float* vp = (const float*)d_in[20];

    conv_attn_fused_kernel<<<B_ * COUT, 512, SMEM_BYTES>>>(
        x,
        wq, gq, bq, mq, vq,
        wk, gk, bk, mk, vk,
        wv, gv, bv, mv, vv,
        wp, gp, bp, mp, vp,
        (float*)d_out);
}